// round 3
// baseline (speedup 1.0000x reference)
#include <cuda_runtime.h>

// HyperbolicResidualAdd: every intermediate vector lies in span{x_row, y_row}.
// Block processes 32 rows: (1) warps reduce X2/Y2/XY per row -> smem,
// (2) warp 0 runs the 32 scalar chains lane-parallel (one row per lane),
// (3) all warps emit out = A*x + B*y re-reading x,y from L2.
// Chain issue cost deduplicated 32x vs warp-per-row SIMT-redundant version.

namespace {

constexpr int D    = 768;
constexpr int VEC  = D / 4;    // 192 float4 per row
constexpr int PL   = VEC / 32; // 6 float4 per lane
constexpr int RPB  = 32;       // rows per block
constexpr int RPW  = 4;        // rows per warp (8 warps)

constexpr float EPSN      = 1e-15f;
constexpr float BALL_EPS  = 1e-5f;
constexpr float TARG_MAX  = 15.0f;
constexpr float ATANH_MAX = 1.0f - 1e-7f;

struct V2 { float a, b; };

__device__ __forceinline__ float softplusf(float v) {
    return (v > 20.f) ? v : log1pf(expf(v));
}

__device__ __forceinline__ float nrm(V2 v, float X2, float Y2, float XY) {
    float n2 = v.a * v.a * X2 + 2.f * v.a * v.b * XY + v.b * v.b * Y2;
    return fmaxf(sqrtf(fmaxf(n2, 0.f)), EPSN);
}

__device__ __forceinline__ float dotc(V2 v, V2 w, float X2, float Y2, float XY) {
    return v.a * w.a * X2 + (v.a * w.b + v.b * w.a) * XY + v.b * w.b * Y2;
}

__device__ __forceinline__ V2 scl(V2 v, float f) { return V2{v.a * f, v.b * f}; }

__device__ __forceinline__ V2 post_clip(V2 v, float X2, float Y2, float XY, float sc) {
    float n = nrm(v, X2, Y2, XY);
    float maxn = (1.0f - BALL_EPS) / sc;
    return scl(v, fminf(1.f, maxn / n));
}

__device__ __forceinline__ V2 pre_clip(V2 v, float X2, float Y2, float XY, float sc) {
    float n = nrm(v, X2, Y2, XY);
    float maxn = TARG_MAX / sc;
    return scl(v, fminf(1.f, maxn / n));
}

__device__ __forceinline__ V2 expmap0(V2 v, float X2, float Y2, float XY, float sc) {
    float n = nrm(v, X2, Y2, XY);
    return scl(v, tanhf(sc * n) / (sc * n));
}

__device__ __forceinline__ V2 mob_smul(float r, V2 v, float X2, float Y2, float XY, float sc) {
    float n = nrm(v, X2, Y2, XY);
    float t = atanhf(fminf(sc * n, ATANH_MAX));
    return scl(v, tanhf(r * t) / (sc * n));
}

__device__ __forceinline__ V2 mob_add(V2 v, V2 w, float X2, float Y2, float XY, float c) {
    float v2 = dotc(v, v, X2, Y2, XY);
    float w2 = dotc(w, w, X2, Y2, XY);
    float vw = dotc(v, w, X2, Y2, XY);
    float cv = 1.f + 2.f * c * vw + c * w2;
    float cw = 1.f - c * v2;
    float den = fmaxf(1.f + 2.f * c * vw + c * c * v2 * w2, EPSN);
    float inv = 1.f / den;
    return V2{(cv * v.a + cw * w.a) * inv, (cv * v.b + cw * w.b) * inv};
}

__global__ void __launch_bounds__(256)
hyperres_kernel(const float* __restrict__ x, const float* __restrict__ y,
                const float* __restrict__ p_curv, const float* __restrict__ p_graw,
                const float* __restrict__ p_gscale, const float* __restrict__ p_scenter,
                float* __restrict__ out, int rows)
{
    __shared__ float sX2[RPB], sY2[RPB], sXY[RPB], sA[RPB], sB[RPB];

    int wid  = threadIdx.x >> 5;
    int lane = threadIdx.x & 31;
    int rowBase = blockIdx.x * RPB;

    // ---------- Phase 1: per-row Gram reductions ----------
#pragma unroll
    for (int k = 0; k < RPW; k++) {
        int idx = wid * RPW + k;
        int r = rowBase + idx;
        if (r < rows) {
            const float4* xr = reinterpret_cast<const float4*>(x) + (size_t)r * VEC + lane;
            const float4* yr = reinterpret_cast<const float4*>(y) + (size_t)r * VEC + lane;
            float X2 = 0.f, Y2 = 0.f, XY = 0.f;
#pragma unroll
            for (int i = 0; i < PL; i++) {
                float4 a = xr[i * 32];
                float4 b = yr[i * 32];
                X2 = fmaf(a.x, a.x, fmaf(a.y, a.y, fmaf(a.z, a.z, fmaf(a.w, a.w, X2))));
                Y2 = fmaf(b.x, b.x, fmaf(b.y, b.y, fmaf(b.z, b.z, fmaf(b.w, b.w, Y2))));
                XY = fmaf(a.x, b.x, fmaf(a.y, b.y, fmaf(a.z, b.z, fmaf(a.w, b.w, XY))));
            }
#pragma unroll
            for (int off = 16; off > 0; off >>= 1) {
                X2 += __shfl_xor_sync(0xffffffffu, X2, off);
                Y2 += __shfl_xor_sync(0xffffffffu, Y2, off);
                XY += __shfl_xor_sync(0xffffffffu, XY, off);
            }
            if (lane == 0) { sX2[idx] = X2; sY2[idx] = Y2; sXY[idx] = XY; }
        }
    }
    __syncthreads();

    // ---------- Phase 2: warp 0, lane-parallel scalar chains ----------
    if (wid == 0) {
        int r = rowBase + lane;
        float X2 = (r < rows) ? sX2[lane] : 1.f;
        float Y2 = (r < rows) ? sY2[lane] : 1.f;
        float XY = (r < rows) ? sXY[lane] : 0.f;

        float c  = softplusf(__ldg(p_curv));
        float sc = sqrtf(c);
        float s  = 1.f / (1.f + expf(-__ldg(p_scenter)));
        float g_max = 1.f + softplusf(__ldg(p_gscale));
        float gamma = g_max * tanhf(__ldg(p_graw));

        V2 xc{1.f, 0.f}, yc{0.f, 1.f};

        V2 hrx = post_clip(expmap0(pre_clip(xc, X2, Y2, XY, sc), X2, Y2, XY, sc), X2, Y2, XY, sc);
        V2 hry = post_clip(expmap0(pre_clip(yc, X2, Y2, XY, sc), X2, Y2, XY, sc), X2, Y2, XY, sc);

        V2 sx = post_clip(mob_smul(s,       hrx, X2, Y2, XY, sc), X2, Y2, XY, sc);
        V2 sy = post_clip(mob_smul(1.f - s, hry, X2, Y2, XY, sc), X2, Y2, XY, sc);
        V2 p  = post_clip(mob_add(sx, sy, X2, Y2, XY, c), X2, Y2, XY, sc);

        V2 mp{-p.a, -p.b};
        V2 xp = post_clip(mob_add(mp, hrx, X2, Y2, XY, c), X2, Y2, XY, sc);
        V2 yp = post_clip(mob_add(mp, hry, X2, Y2, XY, c), X2, Y2, XY, sc);
        V2 ys = post_clip(mob_smul(gamma, yp, X2, Y2, XY, sc), X2, Y2, XY, sc);
        V2 hresp = post_clip(mob_add(xp, ys, X2, Y2, XY, c), X2, Y2, XY, sc);
        V2 hres  = mob_add(p, hresp, X2, Y2, XY, c);
        V2 rr    = post_clip(hres, X2, Y2, XY, sc);

        float nr = nrm(rr, X2, Y2, XY);
        float fl = atanhf(fminf(sc * nr, ATANH_MAX)) / (sc * nr);
        sA[lane] = fl * rr.a;
        sB[lane] = fl * rr.b;
    }
    __syncthreads();

    // ---------- Phase 3: emit out = A*x + B*y (x,y from L2) ----------
#pragma unroll
    for (int k = 0; k < RPW; k++) {
        int idx = wid * RPW + k;
        int r = rowBase + idx;
        if (r < rows) {
            float A = sA[idx], B = sB[idx];
            const float4* xr = reinterpret_cast<const float4*>(x) + (size_t)r * VEC + lane;
            const float4* yr = reinterpret_cast<const float4*>(y) + (size_t)r * VEC + lane;
            float4*       orow = reinterpret_cast<float4*>(out) + (size_t)r * VEC + lane;
#pragma unroll
            for (int i = 0; i < PL; i++) {
                float4 a = xr[i * 32];
                float4 b = yr[i * 32];
                float4 o;
                o.x = fmaf(A, a.x, B * b.x);
                o.y = fmaf(A, a.y, B * b.y);
                o.z = fmaf(A, a.z, B * b.z);
                o.w = fmaf(A, a.w, B * b.w);
                orow[i * 32] = o;
            }
        }
    }
}

} // namespace

extern "C" void kernel_launch(void* const* d_in, const int* in_sizes, int n_in,
                              void* d_out, int out_size)
{
    const float* x       = (const float*)d_in[0];
    const float* y       = (const float*)d_in[1];
    const float* curv    = (const float*)d_in[2];
    const float* graw    = (const float*)d_in[3];
    const float* gscale  = (const float*)d_in[4];
    const float* scenter = (const float*)d_in[5];

    int rows = in_sizes[0] / D;          // 64*577 = 36928
    int blocks = (rows + RPB - 1) / RPB; // 1154

    hyperres_kernel<<<blocks, 256>>>(x, y, curv, graw, gscale, scenter,
                                     (float*)d_out, rows);
}

// round 4
// speedup vs baseline: 1.3014x; 1.3014x over previous
#include <cuda_runtime.h>

// HyperbolicResidualAdd: every intermediate vector lies in span{x_row, y_row}.
// Block = 8 warps, warp-per-row. Phase 1: each warp reduces its row's Gram
// (X2, Y2, XY) -> smem. Phase 2: warp 0 runs all 8 scalar chains lane-parallel
// (lane i = row i). Phase 3: each warp re-reads its row (L1-resident, short
// window) and emits out = A*x + B*y. Chain issue deduplicated 8x; traffic
// stays at the 1-pass minimum because re-reads hit L1.

namespace {

constexpr int D    = 768;
constexpr int VEC  = D / 4;    // 192 float4 per row
constexpr int PL   = VEC / 32; // 6 float4 per lane
constexpr int WPB  = 8;        // warps (= rows) per block

constexpr float EPSN      = 1e-15f;
constexpr float BALL_EPS  = 1e-5f;
constexpr float TARG_MAX  = 15.0f;
constexpr float ATANH_MAX = 1.0f - 1e-7f;

struct V2 { float a, b; };

__device__ __forceinline__ float softplusf(float v) {
    return (v > 20.f) ? v : log1pf(expf(v));
}

__device__ __forceinline__ float nrm(V2 v, float X2, float Y2, float XY) {
    float n2 = v.a * v.a * X2 + 2.f * v.a * v.b * XY + v.b * v.b * Y2;
    return fmaxf(sqrtf(fmaxf(n2, 0.f)), EPSN);
}

__device__ __forceinline__ float dotc(V2 v, V2 w, float X2, float Y2, float XY) {
    return v.a * w.a * X2 + (v.a * w.b + v.b * w.a) * XY + v.b * w.b * Y2;
}

__device__ __forceinline__ V2 scl(V2 v, float f) { return V2{v.a * f, v.b * f}; }

__device__ __forceinline__ V2 post_clip(V2 v, float X2, float Y2, float XY, float sc) {
    float n = nrm(v, X2, Y2, XY);
    float maxn = (1.0f - BALL_EPS) / sc;
    return scl(v, fminf(1.f, maxn / n));
}

__device__ __forceinline__ V2 pre_clip(V2 v, float X2, float Y2, float XY, float sc) {
    float n = nrm(v, X2, Y2, XY);
    float maxn = TARG_MAX / sc;
    return scl(v, fminf(1.f, maxn / n));
}

__device__ __forceinline__ V2 expmap0(V2 v, float X2, float Y2, float XY, float sc) {
    float n = nrm(v, X2, Y2, XY);
    return scl(v, tanhf(sc * n) / (sc * n));
}

__device__ __forceinline__ V2 mob_smul(float r, V2 v, float X2, float Y2, float XY, float sc) {
    float n = nrm(v, X2, Y2, XY);
    float t = atanhf(fminf(sc * n, ATANH_MAX));
    return scl(v, tanhf(r * t) / (sc * n));
}

__device__ __forceinline__ V2 mob_add(V2 v, V2 w, float X2, float Y2, float XY, float c) {
    float v2 = dotc(v, v, X2, Y2, XY);
    float w2 = dotc(w, w, X2, Y2, XY);
    float vw = dotc(v, w, X2, Y2, XY);
    float cv = 1.f + 2.f * c * vw + c * w2;
    float cw = 1.f - c * v2;
    float den = fmaxf(1.f + 2.f * c * vw + c * c * v2 * w2, EPSN);
    float inv = 1.f / den;
    return V2{(cv * v.a + cw * w.a) * inv, (cv * v.b + cw * w.b) * inv};
}

__global__ void __launch_bounds__(256)
hyperres_kernel(const float* __restrict__ x, const float* __restrict__ y,
                const float* __restrict__ p_curv, const float* __restrict__ p_graw,
                const float* __restrict__ p_gscale, const float* __restrict__ p_scenter,
                float* __restrict__ out, int rows)
{
    __shared__ float sX2[WPB], sY2[WPB], sXY[WPB], sA[WPB], sB[WPB];

    int wid  = threadIdx.x >> 5;
    int lane = threadIdx.x & 31;
    int r    = blockIdx.x * WPB + wid;
    bool valid = (r < rows);

    const float4* xr = reinterpret_cast<const float4*>(x) + (size_t)r * VEC + lane;
    const float4* yr = reinterpret_cast<const float4*>(y) + (size_t)r * VEC + lane;

    // ---------- Phase 1: per-row Gram reductions ----------
    if (valid) {
        float X2 = 0.f, Y2 = 0.f, XY = 0.f;
#pragma unroll
        for (int i = 0; i < PL; i++) {
            float4 a = xr[i * 32];
            float4 b = yr[i * 32];
            X2 = fmaf(a.x, a.x, fmaf(a.y, a.y, fmaf(a.z, a.z, fmaf(a.w, a.w, X2))));
            Y2 = fmaf(b.x, b.x, fmaf(b.y, b.y, fmaf(b.z, b.z, fmaf(b.w, b.w, Y2))));
            XY = fmaf(a.x, b.x, fmaf(a.y, b.y, fmaf(a.z, b.z, fmaf(a.w, b.w, XY))));
        }
#pragma unroll
        for (int off = 16; off > 0; off >>= 1) {
            X2 += __shfl_xor_sync(0xffffffffu, X2, off);
            Y2 += __shfl_xor_sync(0xffffffffu, Y2, off);
            XY += __shfl_xor_sync(0xffffffffu, XY, off);
        }
        if (lane == 0) { sX2[wid] = X2; sY2[wid] = Y2; sXY[wid] = XY; }
    }
    __syncthreads();

    // ---------- Phase 2: warp 0 runs 8 chains, one per lane ----------
    if (wid == 0) {
        bool act = (lane < WPB) && (blockIdx.x * WPB + lane < rows);
        float X2 = act ? sX2[lane] : 1.f;
        float Y2 = act ? sY2[lane] : 1.f;
        float XY = act ? sXY[lane] : 0.f;

        float c  = softplusf(__ldg(p_curv));
        float sc = sqrtf(c);
        float s  = 1.f / (1.f + expf(-__ldg(p_scenter)));
        float g_max = 1.f + softplusf(__ldg(p_gscale));
        float gamma = g_max * tanhf(__ldg(p_graw));

        V2 xc{1.f, 0.f}, yc{0.f, 1.f};

        V2 hrx = post_clip(expmap0(pre_clip(xc, X2, Y2, XY, sc), X2, Y2, XY, sc), X2, Y2, XY, sc);
        V2 hry = post_clip(expmap0(pre_clip(yc, X2, Y2, XY, sc), X2, Y2, XY, sc), X2, Y2, XY, sc);

        V2 sx = post_clip(mob_smul(s,       hrx, X2, Y2, XY, sc), X2, Y2, XY, sc);
        V2 sy = post_clip(mob_smul(1.f - s, hry, X2, Y2, XY, sc), X2, Y2, XY, sc);
        V2 p  = post_clip(mob_add(sx, sy, X2, Y2, XY, c), X2, Y2, XY, sc);

        V2 mp{-p.a, -p.b};
        V2 xp = post_clip(mob_add(mp, hrx, X2, Y2, XY, c), X2, Y2, XY, sc);
        V2 yp = post_clip(mob_add(mp, hry, X2, Y2, XY, c), X2, Y2, XY, sc);
        V2 ys = post_clip(mob_smul(gamma, yp, X2, Y2, XY, sc), X2, Y2, XY, sc);
        V2 hresp = post_clip(mob_add(xp, ys, X2, Y2, XY, c), X2, Y2, XY, sc);
        V2 hres  = mob_add(p, hresp, X2, Y2, XY, c);
        V2 rr    = post_clip(hres, X2, Y2, XY, sc);

        float nr = nrm(rr, X2, Y2, XY);
        float fl = atanhf(fminf(sc * nr, ATANH_MAX)) / (sc * nr);
        if (lane < WPB) {
            sA[lane] = fl * rr.a;
            sB[lane] = fl * rr.b;
        }
    }
    __syncthreads();

    // ---------- Phase 3: re-read row (L1 hit) and emit ----------
    if (valid) {
        float A = sA[wid], B = sB[wid];
        float4* orow = reinterpret_cast<float4*>(out) + (size_t)r * VEC + lane;
#pragma unroll
        for (int i = 0; i < PL; i++) {
            float4 a = xr[i * 32];
            float4 b = yr[i * 32];
            float4 o;
            o.x = fmaf(A, a.x, B * b.x);
            o.y = fmaf(A, a.y, B * b.y);
            o.z = fmaf(A, a.z, B * b.z);
            o.w = fmaf(A, a.w, B * b.w);
            orow[i * 32] = o;
        }
    }
}

} // namespace

extern "C" void kernel_launch(void* const* d_in, const int* in_sizes, int n_in,
                              void* d_out, int out_size)
{
    const float* x       = (const float*)d_in[0];
    const float* y       = (const float*)d_in[1];
    const float* curv    = (const float*)d_in[2];
    const float* graw    = (const float*)d_in[3];
    const float* gscale  = (const float*)d_in[4];
    const float* scenter = (const float*)d_in[5];

    int rows = in_sizes[0] / D;            // 64*577 = 36928
    int blocks = (rows + WPB - 1) / WPB;   // 4616

    hyperres_kernel<<<blocks, 256>>>(x, y, curv, graw, gscale, scenter,
                                     (float*)d_out, rows);
}

// round 5
// speedup vs baseline: 1.3366x; 1.0270x over previous
#include <cuda_runtime.h>

// HyperbolicResidualAdd: every intermediate vector lies in span{x_row, y_row}.
// Block = 8 warps, warp-per-row. Phase 1: each warp reduces its row's Gram
// (X2, Y2, XY) -> smem. Phase 2: warp 0 runs all 8 scalar chains lane-parallel
// using short-latency MUFU intrinsics (__expf/__logf/__fdividef) -- the libm
// tanhf/atanhf serial chain was the R4 bottleneck (DRAM capped at 65% while
// warps waited at the barrier). Phase 3: each warp re-reads its row (L1/L2)
// and emits out = A*x + B*y.

namespace {

constexpr int D    = 768;
constexpr int VEC  = D / 4;    // 192 float4 per row
constexpr int PL   = VEC / 32; // 6 float4 per lane
constexpr int WPB  = 8;        // warps (= rows) per block

constexpr float EPSN      = 1e-15f;
constexpr float BALL_EPS  = 1e-5f;
constexpr float TARG_MAX  = 15.0f;
constexpr float ATANH_MAX = 1.0f - 1e-7f;

struct V2 { float a, b; };

// ---- short-latency transcendentals (MUFU-based, ~2 ulp) ----
__device__ __forceinline__ float fast_tanh(float v) {
    // args here are in [0, 15]; e^{2v} <= e^30 ~ 1.1e13, no overflow
    float e = __expf(2.f * v);
    return __fdividef(e - 1.f, e + 1.f);
}
__device__ __forceinline__ float fast_atanh(float v) {
    // v in [0, 1-1e-7]
    return 0.5f * __logf(__fdividef(1.f + v, 1.f - v));
}

__device__ __forceinline__ float softplusf(float v) {
    return (v > 20.f) ? v : log1pf(expf(v));
}

__device__ __forceinline__ float nrm(V2 v, float X2, float Y2, float XY) {
    float n2 = v.a * v.a * X2 + 2.f * v.a * v.b * XY + v.b * v.b * Y2;
    return fmaxf(sqrtf(fmaxf(n2, 0.f)), EPSN);
}

__device__ __forceinline__ float dotc(V2 v, V2 w, float X2, float Y2, float XY) {
    return v.a * w.a * X2 + (v.a * w.b + v.b * w.a) * XY + v.b * w.b * Y2;
}

__device__ __forceinline__ V2 scl(V2 v, float f) { return V2{v.a * f, v.b * f}; }

__device__ __forceinline__ V2 post_clip(V2 v, float X2, float Y2, float XY, float sc) {
    float n = nrm(v, X2, Y2, XY);
    float maxn = (1.0f - BALL_EPS) / sc;
    return scl(v, fminf(1.f, __fdividef(maxn, n)));
}

__device__ __forceinline__ V2 pre_clip(V2 v, float X2, float Y2, float XY, float sc) {
    float n = nrm(v, X2, Y2, XY);
    float maxn = TARG_MAX / sc;
    return scl(v, fminf(1.f, __fdividef(maxn, n)));
}

__device__ __forceinline__ V2 expmap0(V2 v, float X2, float Y2, float XY, float sc) {
    float n = nrm(v, X2, Y2, XY);
    return scl(v, __fdividef(fast_tanh(sc * n), sc * n));
}

__device__ __forceinline__ V2 mob_smul(float r, V2 v, float X2, float Y2, float XY, float sc) {
    float n = nrm(v, X2, Y2, XY);
    float t = fast_atanh(fminf(sc * n, ATANH_MAX));
    return scl(v, __fdividef(fast_tanh(r * t), sc * n));
}

__device__ __forceinline__ V2 mob_add(V2 v, V2 w, float X2, float Y2, float XY, float c) {
    float v2 = dotc(v, v, X2, Y2, XY);
    float w2 = dotc(w, w, X2, Y2, XY);
    float vw = dotc(v, w, X2, Y2, XY);
    float cv = 1.f + 2.f * c * vw + c * w2;
    float cw = 1.f - c * v2;
    float den = fmaxf(1.f + 2.f * c * vw + c * c * v2 * w2, EPSN);
    float inv = __fdividef(1.f, den);
    return V2{(cv * v.a + cw * w.a) * inv, (cv * v.b + cw * w.b) * inv};
}

__global__ void __launch_bounds__(256)
hyperres_kernel(const float* __restrict__ x, const float* __restrict__ y,
                const float* __restrict__ p_curv, const float* __restrict__ p_graw,
                const float* __restrict__ p_gscale, const float* __restrict__ p_scenter,
                float* __restrict__ out, int rows)
{
    __shared__ float sX2[WPB], sY2[WPB], sXY[WPB], sA[WPB], sB[WPB];

    int wid  = threadIdx.x >> 5;
    int lane = threadIdx.x & 31;
    int r    = blockIdx.x * WPB + wid;
    bool valid = (r < rows);

    const float4* xr = reinterpret_cast<const float4*>(x) + (size_t)r * VEC + lane;
    const float4* yr = reinterpret_cast<const float4*>(y) + (size_t)r * VEC + lane;

    // ---------- Phase 1: per-row Gram reductions ----------
    if (valid) {
        float X2 = 0.f, Y2 = 0.f, XY = 0.f;
#pragma unroll
        for (int i = 0; i < PL; i++) {
            float4 a = xr[i * 32];
            float4 b = yr[i * 32];
            X2 = fmaf(a.x, a.x, fmaf(a.y, a.y, fmaf(a.z, a.z, fmaf(a.w, a.w, X2))));
            Y2 = fmaf(b.x, b.x, fmaf(b.y, b.y, fmaf(b.z, b.z, fmaf(b.w, b.w, Y2))));
            XY = fmaf(a.x, b.x, fmaf(a.y, b.y, fmaf(a.z, b.z, fmaf(a.w, b.w, XY))));
        }
#pragma unroll
        for (int off = 16; off > 0; off >>= 1) {
            X2 += __shfl_xor_sync(0xffffffffu, X2, off);
            Y2 += __shfl_xor_sync(0xffffffffu, Y2, off);
            XY += __shfl_xor_sync(0xffffffffu, XY, off);
        }
        if (lane == 0) { sX2[wid] = X2; sY2[wid] = Y2; sXY[wid] = XY; }
    }
    __syncthreads();

    // ---------- Phase 2: warp 0 runs 8 chains, one per lane ----------
    if (wid == 0) {
        bool act = (lane < WPB) && (blockIdx.x * WPB + lane < rows);
        float X2 = act ? sX2[lane] : 1.f;
        float Y2 = act ? sY2[lane] : 1.f;
        float XY = act ? sXY[lane] : 0.f;

        float c  = softplusf(__ldg(p_curv));
        float sc = sqrtf(c);
        float s  = __fdividef(1.f, 1.f + __expf(-__ldg(p_scenter)));
        float g_max = 1.f + softplusf(__ldg(p_gscale));
        float gamma = g_max * fast_tanh(__ldg(p_graw));

        V2 xc{1.f, 0.f}, yc{0.f, 1.f};

        V2 hrx = post_clip(expmap0(pre_clip(xc, X2, Y2, XY, sc), X2, Y2, XY, sc), X2, Y2, XY, sc);
        V2 hry = post_clip(expmap0(pre_clip(yc, X2, Y2, XY, sc), X2, Y2, XY, sc), X2, Y2, XY, sc);

        V2 sx = post_clip(mob_smul(s,       hrx, X2, Y2, XY, sc), X2, Y2, XY, sc);
        V2 sy = post_clip(mob_smul(1.f - s, hry, X2, Y2, XY, sc), X2, Y2, XY, sc);
        V2 p  = post_clip(mob_add(sx, sy, X2, Y2, XY, c), X2, Y2, XY, sc);

        V2 mp{-p.a, -p.b};
        V2 xp = post_clip(mob_add(mp, hrx, X2, Y2, XY, c), X2, Y2, XY, sc);
        V2 yp = post_clip(mob_add(mp, hry, X2, Y2, XY, c), X2, Y2, XY, sc);
        V2 ys = post_clip(mob_smul(gamma, yp, X2, Y2, XY, sc), X2, Y2, XY, sc);
        V2 hresp = post_clip(mob_add(xp, ys, X2, Y2, XY, c), X2, Y2, XY, sc);
        V2 hres  = mob_add(p, hresp, X2, Y2, XY, c);
        V2 rr    = post_clip(hres, X2, Y2, XY, sc);

        float nr = nrm(rr, X2, Y2, XY);
        float fl = __fdividef(fast_atanh(fminf(sc * nr, ATANH_MAX)), sc * nr);
        if (lane < WPB) {
            sA[lane] = fl * rr.a;
            sB[lane] = fl * rr.b;
        }
    }
    __syncthreads();

    // ---------- Phase 3: re-read row (L1/L2 hit) and emit ----------
    if (valid) {
        float A = sA[wid], B = sB[wid];
        float4* orow = reinterpret_cast<float4*>(out) + (size_t)r * VEC + lane;
#pragma unroll
        for (int i = 0; i < PL; i++) {
            float4 a = xr[i * 32];
            float4 b = yr[i * 32];
            float4 o;
            o.x = fmaf(A, a.x, B * b.x);
            o.y = fmaf(A, a.y, B * b.y);
            o.z = fmaf(A, a.z, B * b.z);
            o.w = fmaf(A, a.w, B * b.w);
            orow[i * 32] = o;
        }
    }
}

} // namespace

extern "C" void kernel_launch(void* const* d_in, const int* in_sizes, int n_in,
                              void* d_out, int out_size)
{
    const float* x       = (const float*)d_in[0];
    const float* y       = (const float*)d_in[1];
    const float* curv    = (const float*)d_in[2];
    const float* graw    = (const float*)d_in[3];
    const float* gscale  = (const float*)d_in[4];
    const float* scenter = (const float*)d_in[5];

    int rows = in_sizes[0] / D;            // 64*577 = 36928
    int blocks = (rows + WPB - 1) / WPB;   // 4616

    hyperres_kernel<<<blocks, 256>>>(x, y, curv, graw, gscale, scenter,
                                     (float*)d_out, rows);
}

// round 6
// speedup vs baseline: 1.5421x; 1.1538x over previous
#include <cuda_runtime.h>

// HyperbolicResidualAdd: every intermediate vector lies in span{x_row, y_row}.
// Block = 8 warps, warp-per-row. Phase 1: each warp loads its row once,
// keeps x in REGISTERS, stages y in SHARED MEMORY, reduces Gram (X2,Y2,XY).
// Phase 2: warp 0 runs all 8 scalar chains lane-parallel with MUFU fast-math.
// Phase 3: emit out = A*x(reg) + B*y(smem) -- zero L1/L2 re-read traffic.
// DRAM touched exactly once per element by construction.

namespace {

constexpr int D    = 768;
constexpr int VEC  = D / 4;    // 192 float4 per row
constexpr int PL   = VEC / 32; // 6 float4 per lane
constexpr int WPB  = 8;        // warps (= rows) per block

constexpr float EPSN      = 1e-15f;
constexpr float BALL_EPS  = 1e-5f;
constexpr float TARG_MAX  = 15.0f;
constexpr float ATANH_MAX = 1.0f - 1e-7f;

struct V2 { float a, b; };

__device__ __forceinline__ float fast_tanh(float v) {
    float e = __expf(2.f * v);
    return __fdividef(e - 1.f, e + 1.f);
}
__device__ __forceinline__ float fast_atanh(float v) {
    return 0.5f * __logf(__fdividef(1.f + v, 1.f - v));
}
__device__ __forceinline__ float softplusf(float v) {
    return (v > 20.f) ? v : log1pf(expf(v));
}

__device__ __forceinline__ float nrm(V2 v, float X2, float Y2, float XY) {
    float n2 = v.a * v.a * X2 + 2.f * v.a * v.b * XY + v.b * v.b * Y2;
    return fmaxf(sqrtf(fmaxf(n2, 0.f)), EPSN);
}
__device__ __forceinline__ float dotc(V2 v, V2 w, float X2, float Y2, float XY) {
    return v.a * w.a * X2 + (v.a * w.b + v.b * w.a) * XY + v.b * w.b * Y2;
}
__device__ __forceinline__ V2 scl(V2 v, float f) { return V2{v.a * f, v.b * f}; }

__device__ __forceinline__ V2 post_clip(V2 v, float X2, float Y2, float XY, float sc) {
    float n = nrm(v, X2, Y2, XY);
    float maxn = (1.0f - BALL_EPS) / sc;
    return scl(v, fminf(1.f, __fdividef(maxn, n)));
}
__device__ __forceinline__ V2 pre_clip(V2 v, float X2, float Y2, float XY, float sc) {
    float n = nrm(v, X2, Y2, XY);
    float maxn = TARG_MAX / sc;
    return scl(v, fminf(1.f, __fdividef(maxn, n)));
}
__device__ __forceinline__ V2 expmap0(V2 v, float X2, float Y2, float XY, float sc) {
    float n = nrm(v, X2, Y2, XY);
    return scl(v, __fdividef(fast_tanh(sc * n), sc * n));
}
__device__ __forceinline__ V2 mob_smul(float r, V2 v, float X2, float Y2, float XY, float sc) {
    float n = nrm(v, X2, Y2, XY);
    float t = fast_atanh(fminf(sc * n, ATANH_MAX));
    return scl(v, __fdividef(fast_tanh(r * t), sc * n));
}
__device__ __forceinline__ V2 mob_add(V2 v, V2 w, float X2, float Y2, float XY, float c) {
    float v2 = dotc(v, v, X2, Y2, XY);
    float w2 = dotc(w, w, X2, Y2, XY);
    float vw = dotc(v, w, X2, Y2, XY);
    float cv = 1.f + 2.f * c * vw + c * w2;
    float cw = 1.f - c * v2;
    float den = fmaxf(1.f + 2.f * c * vw + c * c * v2 * w2, EPSN);
    float inv = __fdividef(1.f, den);
    return V2{(cv * v.a + cw * w.a) * inv, (cv * v.b + cw * w.b) * inv};
}

__global__ void __launch_bounds__(256)
hyperres_kernel(const float* __restrict__ x, const float* __restrict__ y,
                const float* __restrict__ p_curv, const float* __restrict__ p_graw,
                const float* __restrict__ p_gscale, const float* __restrict__ p_scenter,
                float* __restrict__ out, int rows)
{
    __shared__ float4 sy[WPB * VEC];                 // 24 KB: y staged on-chip
    __shared__ float sX2[WPB], sY2[WPB], sXY[WPB], sA[WPB], sB[WPB];

    int wid  = threadIdx.x >> 5;
    int lane = threadIdx.x & 31;
    int r    = blockIdx.x * WPB + wid;
    bool valid = (r < rows);

    const float4* xr = reinterpret_cast<const float4*>(x) + (size_t)r * VEC + lane;
    const float4* yr = reinterpret_cast<const float4*>(y) + (size_t)r * VEC + lane;
    float4* syw = sy + wid * VEC + lane;

    float4 xv[PL];

    // ---------- Phase 1: load once; x -> regs, y -> smem; Gram reduce ----------
    if (valid) {
        float4 bv[PL];
#pragma unroll
        for (int i = 0; i < PL; i++) xv[i] = xr[i * 32];
#pragma unroll
        for (int i = 0; i < PL; i++) bv[i] = yr[i * 32];

        float X2 = 0.f, Y2 = 0.f, XY = 0.f;
#pragma unroll
        for (int i = 0; i < PL; i++) {
            float4 a = xv[i], b = bv[i];
            syw[i * 32] = b;
            X2 = fmaf(a.x, a.x, fmaf(a.y, a.y, fmaf(a.z, a.z, fmaf(a.w, a.w, X2))));
            Y2 = fmaf(b.x, b.x, fmaf(b.y, b.y, fmaf(b.z, b.z, fmaf(b.w, b.w, Y2))));
            XY = fmaf(a.x, b.x, fmaf(a.y, b.y, fmaf(a.z, b.z, fmaf(a.w, b.w, XY))));
        }
#pragma unroll
        for (int off = 16; off > 0; off >>= 1) {
            X2 += __shfl_xor_sync(0xffffffffu, X2, off);
            Y2 += __shfl_xor_sync(0xffffffffu, Y2, off);
            XY += __shfl_xor_sync(0xffffffffu, XY, off);
        }
        if (lane == 0) { sX2[wid] = X2; sY2[wid] = Y2; sXY[wid] = XY; }
    }
    __syncthreads();

    // ---------- Phase 2: warp 0 runs 8 chains, one per lane ----------
    if (wid == 0) {
        bool act = (lane < WPB) && (blockIdx.x * WPB + lane < rows);
        float X2 = act ? sX2[lane] : 1.f;
        float Y2 = act ? sY2[lane] : 1.f;
        float XY = act ? sXY[lane] : 0.f;

        float c  = softplusf(__ldg(p_curv));
        float sc = sqrtf(c);
        float s  = __fdividef(1.f, 1.f + __expf(-__ldg(p_scenter)));
        float g_max = 1.f + softplusf(__ldg(p_gscale));
        float gamma = g_max * fast_tanh(__ldg(p_graw));

        V2 xc{1.f, 0.f}, yc{0.f, 1.f};

        V2 hrx = post_clip(expmap0(pre_clip(xc, X2, Y2, XY, sc), X2, Y2, XY, sc), X2, Y2, XY, sc);
        V2 hry = post_clip(expmap0(pre_clip(yc, X2, Y2, XY, sc), X2, Y2, XY, sc), X2, Y2, XY, sc);

        V2 sx = post_clip(mob_smul(s,       hrx, X2, Y2, XY, sc), X2, Y2, XY, sc);
        V2 syv = post_clip(mob_smul(1.f - s, hry, X2, Y2, XY, sc), X2, Y2, XY, sc);
        V2 p  = post_clip(mob_add(sx, syv, X2, Y2, XY, c), X2, Y2, XY, sc);

        V2 mp{-p.a, -p.b};
        V2 xp = post_clip(mob_add(mp, hrx, X2, Y2, XY, c), X2, Y2, XY, sc);
        V2 yp = post_clip(mob_add(mp, hry, X2, Y2, XY, c), X2, Y2, XY, sc);
        V2 ys = post_clip(mob_smul(gamma, yp, X2, Y2, XY, sc), X2, Y2, XY, sc);
        V2 hresp = post_clip(mob_add(xp, ys, X2, Y2, XY, c), X2, Y2, XY, sc);
        V2 hres  = mob_add(p, hresp, X2, Y2, XY, c);
        V2 rr    = post_clip(hres, X2, Y2, XY, sc);

        float nr = nrm(rr, X2, Y2, XY);
        float fl = __fdividef(fast_atanh(fminf(sc * nr, ATANH_MAX)), sc * nr);
        if (lane < WPB) {
            sA[lane] = fl * rr.a;
            sB[lane] = fl * rr.b;
        }
    }
    __syncthreads();

    // ---------- Phase 3: emit out = A*x(reg) + B*y(smem) ----------
    if (valid) {
        float A = sA[wid], B = sB[wid];
        float4* orow = reinterpret_cast<float4*>(out) + (size_t)r * VEC + lane;
#pragma unroll
        for (int i = 0; i < PL; i++) {
            float4 a = xv[i];
            float4 b = syw[i * 32];
            float4 o;
            o.x = fmaf(A, a.x, B * b.x);
            o.y = fmaf(A, a.y, B * b.y);
            o.z = fmaf(A, a.z, B * b.z);
            o.w = fmaf(A, a.w, B * b.w);
            orow[i * 32] = o;
        }
    }
}

} // namespace

extern "C" void kernel_launch(void* const* d_in, const int* in_sizes, int n_in,
                              void* d_out, int out_size)
{
    const float* x       = (const float*)d_in[0];
    const float* y       = (const float*)d_in[1];
    const float* curv    = (const float*)d_in[2];
    const float* graw    = (const float*)d_in[3];
    const float* gscale  = (const float*)d_in[4];
    const float* scenter = (const float*)d_in[5];

    int rows = in_sizes[0] / D;            // 64*577 = 36928
    int blocks = (rows + WPB - 1) / WPB;   // 4616

    hyperres_kernel<<<blocks, 256>>>(x, y, curv, graw, gscale, scenter,
                                     (float*)d_out, rows);
}